// round 1
// baseline (speedup 1.0000x reference)
#include <cuda_runtime.h>
#include <cuda_bf16.h>

// ---------------------------------------------------------------------------
// MoE segment-linear:  y[n,o] = sum_e coeff[seg(n),e] * dot(x[n,:], W[e,o,:]) + bias[o]
// Strategy: mix weights per segment (cheap), then B per-segment fp32 GEMMs.
// ---------------------------------------------------------------------------

#define MAX_WMIX_ELEMS (16u * 1024u * 1024u)   // B*O*I = 16M floats = 64 MB
#define MAX_TILES 4096
#define MAX_COEFF 512

__device__ float g_wmix[MAX_WMIX_ELEMS];
__device__ int   g_tile_row[MAX_TILES];
__device__ int   g_tile_rows[MAX_TILES];
__device__ int   g_tile_seg[MAX_TILES];
__device__ int   g_tile_cnt;

// ---------------------------------------------------------------------------
// Kernel 1: mix weights.  g_wmix[b, o, i] = sum_e coeff[b,e] * W[e, o, i]
// Reads W once (32MB), writes B mixed copies (64MB). HBM-bound, ~15us.
// ---------------------------------------------------------------------------
__global__ void mix_kernel(const float* __restrict__ W,
                           const float* __restrict__ coeff,
                           int E, int B, long long OI4 /* O*I/4 */) {
    long long idx = (long long)blockIdx.x * blockDim.x + threadIdx.x;

    __shared__ float sc[MAX_COEFF];
    int ncoef = B * E;
    for (int i = threadIdx.x; i < ncoef; i += blockDim.x) sc[i] = coeff[i];
    __syncthreads();

    if (idx >= OI4) return;

    float4 w[8];
#pragma unroll
    for (int e = 0; e < 8; e++) {
        if (e < E)
            w[e] = reinterpret_cast<const float4*>(W)[(long long)e * OI4 + idx];
        else
            w[e] = make_float4(0.f, 0.f, 0.f, 0.f);
    }

    for (int b = 0; b < B; b++) {
        float4 acc = make_float4(0.f, 0.f, 0.f, 0.f);
#pragma unroll
        for (int e = 0; e < 8; e++) {
            if (e < E) {
                float c = sc[b * E + e];
                acc.x += c * w[e].x;
                acc.y += c * w[e].y;
                acc.z += c * w[e].z;
                acc.w += c * w[e].w;
            }
        }
        reinterpret_cast<float4*>(g_wmix)[(long long)b * OI4 + idx] = acc;
    }
}

// ---------------------------------------------------------------------------
// Kernel 2: build the row-tile table from mole_sizes so that every GEMM
// row-tile lies entirely within one segment (general w.r.t. dynamic sizes).
// ---------------------------------------------------------------------------
#define BM 128
#define BN 128
#define BK 16

__global__ void build_tiles(const int* __restrict__ mole_sizes, int B) {
    if (threadIdx.x != 0 || blockIdx.x != 0) return;
    int cnt = 0;
    int off = 0;
    for (int b = 0; b < B; b++) {
        int sz = mole_sizes[b];
        for (int r = 0; r < sz; r += BM) {
            if (cnt < MAX_TILES) {
                g_tile_row[cnt]  = off + r;
                g_tile_rows[cnt] = (sz - r) < BM ? (sz - r) : BM;
                g_tile_seg[cnt]  = b;
            }
            cnt++;
        }
        off += sz;
    }
    g_tile_cnt = cnt < MAX_TILES ? cnt : MAX_TILES;
}

// ---------------------------------------------------------------------------
// Kernel 3: fp32 SGEMM per row-tile.
//   y[tile rows, col tile] = x_tile @ Wmix[seg]^T + bias
//   x:    [N, I]  (K contiguous)
//   Wmix: [B][O][I]  (K contiguous)  -> B operand rows are output columns
// 128x128 block tile, BK=16, 256 threads, 8x8 per-thread microtile.
// ---------------------------------------------------------------------------
#define PAD 4

__global__ __launch_bounds__(256, 2)
void sgemm_kernel(const float* __restrict__ x,
                  const float* __restrict__ bias,
                  float* __restrict__ y,
                  int I, int O) {
    int t = blockIdx.y;
    if (t >= g_tile_cnt) return;

    const int row0  = g_tile_row[t];
    const int nrows = g_tile_rows[t];
    const int seg   = g_tile_seg[t];
    const int col0  = blockIdx.x * BN;

    const float* __restrict__ Wb = g_wmix + (long long)seg * O * I;

    __shared__ float As[BK][BM + PAD];
    __shared__ float Bs[BK][BN + PAD];

    const int tid = threadIdx.x;
    const int tx  = tid & 15;   // column group (0..15)
    const int ty  = tid >> 4;   // row group    (0..15)

    float acc[8][8];
#pragma unroll
    for (int i = 0; i < 8; i++)
#pragma unroll
        for (int j = 0; j < 8; j++) acc[i][j] = 0.f;

    for (int k0 = 0; k0 < I; k0 += BK) {
        // --- load A tile (128 rows x 16 k), 2 float4 per thread, transpose ---
#pragma unroll
        for (int l = 0; l < 2; l++) {
            int f  = tid + l * 256;       // float4 index in tile (0..511)
            int r  = f >> 2;              // row within tile (0..127)
            int kc = (f & 3) << 2;        // k offset within BK (0,4,8,12)
            float4 v = make_float4(0.f, 0.f, 0.f, 0.f);
            if (r < nrows)
                v = *reinterpret_cast<const float4*>(
                        x + (long long)(row0 + r) * I + k0 + kc);
            As[kc + 0][r] = v.x;
            As[kc + 1][r] = v.y;
            As[kc + 2][r] = v.z;
            As[kc + 3][r] = v.w;
        }
        // --- load B tile (128 out-cols x 16 k), transpose ---
#pragma unroll
        for (int l = 0; l < 2; l++) {
            int f  = tid + l * 256;
            int c  = f >> 2;
            int kc = (f & 3) << 2;
            float4 v = make_float4(0.f, 0.f, 0.f, 0.f);
            if (col0 + c < O)
                v = *reinterpret_cast<const float4*>(
                        Wb + (long long)(col0 + c) * I + k0 + kc);
            Bs[kc + 0][c] = v.x;
            Bs[kc + 1][c] = v.y;
            Bs[kc + 2][c] = v.z;
            Bs[kc + 3][c] = v.w;
        }
        __syncthreads();

#pragma unroll
        for (int kk = 0; kk < BK; kk++) {
            float a[8], b[8];
            float4 a0 = *reinterpret_cast<const float4*>(&As[kk][ty * 8]);
            float4 a1 = *reinterpret_cast<const float4*>(&As[kk][ty * 8 + 4]);
            float4 b0 = *reinterpret_cast<const float4*>(&Bs[kk][tx * 8]);
            float4 b1 = *reinterpret_cast<const float4*>(&Bs[kk][tx * 8 + 4]);
            a[0]=a0.x; a[1]=a0.y; a[2]=a0.z; a[3]=a0.w;
            a[4]=a1.x; a[5]=a1.y; a[6]=a1.z; a[7]=a1.w;
            b[0]=b0.x; b[1]=b0.y; b[2]=b0.z; b[3]=b0.w;
            b[4]=b1.x; b[5]=b1.y; b[6]=b1.z; b[7]=b1.w;
#pragma unroll
            for (int i = 0; i < 8; i++)
#pragma unroll
                for (int j = 0; j < 8; j++)
                    acc[i][j] += a[i] * b[j];
        }
        __syncthreads();
    }

    // --- epilogue: add bias, store ---
    float bj[8];
#pragma unroll
    for (int j = 0; j < 8; j++) {
        int c = col0 + tx * 8 + j;
        bj[j] = (c < O) ? bias[c] : 0.f;
    }

#pragma unroll
    for (int i = 0; i < 8; i++) {
        int rloc = ty * 8 + i;
        if (rloc >= nrows) continue;
        long long base = (long long)(row0 + rloc) * O + col0 + tx * 8;
        if (col0 + tx * 8 + 7 < O) {
            float4 v0, v1;
            v0.x = acc[i][0] + bj[0];
            v0.y = acc[i][1] + bj[1];
            v0.z = acc[i][2] + bj[2];
            v0.w = acc[i][3] + bj[3];
            v1.x = acc[i][4] + bj[4];
            v1.y = acc[i][5] + bj[5];
            v1.z = acc[i][6] + bj[6];
            v1.w = acc[i][7] + bj[7];
            *reinterpret_cast<float4*>(y + base)     = v0;
            *reinterpret_cast<float4*>(y + base + 4) = v1;
        } else {
#pragma unroll
            for (int j = 0; j < 8; j++) {
                int c = col0 + tx * 8 + j;
                if (c < O) y[base + j] = acc[i][j] + bj[j];
            }
        }
    }
}

// ---------------------------------------------------------------------------
// Launch
// ---------------------------------------------------------------------------
extern "C" void kernel_launch(void* const* d_in, const int* in_sizes, int n_in,
                              void* d_out, int out_size) {
    const float* x      = (const float*)d_in[0];          // [N, I]
    const float* W      = (const float*)d_in[1];          // [E, O, I]
    const float* bias   = (const float*)d_in[2];          // [O]
    const float* coeff  = (const float*)d_in[3];          // [B, E]
    const int*   msize  = (const int*)  d_in[4];          // [B]

    const int O = in_sizes[2];
    const int N = out_size / O;
    const int I = in_sizes[0] / N;
    const int E = in_sizes[1] / (O * I);
    const int B = in_sizes[3] / E;

    // 1) mix weights per segment
    {
        long long OI4 = (long long)O * I / 4;
        int threads = 256;
        int blocks  = (int)((OI4 + threads - 1) / threads);
        mix_kernel<<<blocks, threads>>>(W, coeff, E, B, OI4);
    }

    // 2) build row-tile table from mole_sizes
    build_tiles<<<1, 32>>>(msize, B);

    // 3) per-tile GEMM (+bias)
    {
        int maxTiles = (N + BM - 1) / BM + B;   // upper bound on tile count
        dim3 grid((O + BN - 1) / BN, maxTiles);
        sgemm_kernel<<<grid, 256>>>(x, bias, (float*)d_out, I, O);
    }
}

// round 3
// speedup vs baseline: 2.7839x; 2.7839x over previous
#include <cuda_runtime.h>
#include <cuda_bf16.h>
#include <cstdint>

// ===========================================================================
// MoE segment-linear via mma.sync bf16 split-precision GEMM (plain-sm_103 ISA).
//   y[n,o] = sum_e coeff[seg(n),e] * dot(x[n,:], W[e,o,:]) + bias[o]
// 1) split x into bf16 hi/lo
// 2) mix weights per segment -> bf16 hi/lo
// 3) per-tile GEMM: D = Ahi*Bhi + Ahi*Blo + Alo*Bhi (fp32 reg accum) + bias
// ===========================================================================

#define MAX_X_ELEMS (16u * 1024u * 1024u)   // N*I
#define MAX_W_ELEMS (16u * 1024u * 1024u)   // B*O*I
#define MAX_TILES 4096
#define MAX_COEFF 512

__device__ __nv_bfloat16 g_xhi[MAX_X_ELEMS];
__device__ __nv_bfloat16 g_xlo[MAX_X_ELEMS];
__device__ __nv_bfloat16 g_whi[MAX_W_ELEMS];
__device__ __nv_bfloat16 g_wlo[MAX_W_ELEMS];
__device__ int g_tile_row[MAX_TILES];
__device__ int g_tile_rows[MAX_TILES];
__device__ int g_tile_seg[MAX_TILES];
__device__ int g_tile_cnt;

// ---------------------------------------------------------------------------
// Small helpers (baseline PTX only — nothing arch-'a'-gated)
// ---------------------------------------------------------------------------
__device__ __forceinline__ uint32_t smem_u32(const void* p) {
    uint32_t a;
    asm("{ .reg .u64 t; cvta.to.shared.u64 t, %1; cvt.u32.u64 %0, t; }"
        : "=r"(a) : "l"(p));
    return a;
}

__device__ __forceinline__ void cp16(uint32_t dst, const void* src, int szbytes) {
    asm volatile("cp.async.cg.shared.global [%0], [%1], 16, %2;"
                 :: "r"(dst), "l"(src), "r"(szbytes));
}
#define CP_COMMIT() asm volatile("cp.async.commit_group;")
#define CP_WAIT(n)  asm volatile("cp.async.wait_group %0;" :: "n"(n))

__device__ __forceinline__ void ldm4(uint32_t* r, uint32_t addr) {
    asm volatile("ldmatrix.sync.aligned.m8n8.x4.shared.b16 {%0,%1,%2,%3}, [%4];"
                 : "=r"(r[0]), "=r"(r[1]), "=r"(r[2]), "=r"(r[3]) : "r"(addr));
}

__device__ __forceinline__ void mma_bf16(float* c, const uint32_t* a,
                                         uint32_t b0, uint32_t b1) {
    asm volatile(
        "mma.sync.aligned.m16n8k16.row.col.f32.bf16.bf16.f32 "
        "{%0,%1,%2,%3}, {%4,%5,%6,%7}, {%8,%9}, {%0,%1,%2,%3};"
        : "+f"(c[0]), "+f"(c[1]), "+f"(c[2]), "+f"(c[3])
        : "r"(a[0]), "r"(a[1]), "r"(a[2]), "r"(a[3]), "r"(b0), "r"(b1));
}

// ---------------------------------------------------------------------------
// Kernel 1: split x into bf16 hi/lo
// ---------------------------------------------------------------------------
__global__ void split_x_kernel(const float* __restrict__ x, long long n4) {
    long long idx = (long long)blockIdx.x * blockDim.x + threadIdx.x;
    if (idx >= n4) return;
    float4 v = reinterpret_cast<const float4*>(x)[idx];
    __nv_bfloat16 h0 = __float2bfloat16(v.x);
    __nv_bfloat16 h1 = __float2bfloat16(v.y);
    __nv_bfloat16 h2 = __float2bfloat16(v.z);
    __nv_bfloat16 h3 = __float2bfloat16(v.w);
    __nv_bfloat16 l0 = __float2bfloat16(v.x - __bfloat162float(h0));
    __nv_bfloat16 l1 = __float2bfloat16(v.y - __bfloat162float(h1));
    __nv_bfloat16 l2 = __float2bfloat16(v.z - __bfloat162float(h2));
    __nv_bfloat16 l3 = __float2bfloat16(v.w - __bfloat162float(h3));
    __nv_bfloat162* hi2 = reinterpret_cast<__nv_bfloat162*>(g_xhi);
    __nv_bfloat162* lo2 = reinterpret_cast<__nv_bfloat162*>(g_xlo);
    hi2[idx * 2 + 0] = __halves2bfloat162(h0, h1);
    hi2[idx * 2 + 1] = __halves2bfloat162(h2, h3);
    lo2[idx * 2 + 0] = __halves2bfloat162(l0, l1);
    lo2[idx * 2 + 1] = __halves2bfloat162(l2, l3);
}

// ---------------------------------------------------------------------------
// Kernel 2: mix weights per segment, store bf16 hi/lo
// ---------------------------------------------------------------------------
__global__ void mix_kernel(const float* __restrict__ W,
                           const float* __restrict__ coeff,
                           int E, int B, long long OI4) {
    long long idx = (long long)blockIdx.x * blockDim.x + threadIdx.x;

    __shared__ float sc[MAX_COEFF];
    int ncoef = B * E;
    for (int i = threadIdx.x; i < ncoef; i += blockDim.x) sc[i] = coeff[i];
    __syncthreads();
    if (idx >= OI4) return;

    float4 w[8];
#pragma unroll
    for (int e = 0; e < 8; e++) {
        if (e < E)
            w[e] = reinterpret_cast<const float4*>(W)[(long long)e * OI4 + idx];
        else
            w[e] = make_float4(0.f, 0.f, 0.f, 0.f);
    }

    long long OI = OI4 * 4;
    for (int b = 0; b < B; b++) {
        float4 acc = make_float4(0.f, 0.f, 0.f, 0.f);
#pragma unroll
        for (int e = 0; e < 8; e++) {
            if (e < E) {
                float c = sc[b * E + e];
                acc.x += c * w[e].x; acc.y += c * w[e].y;
                acc.z += c * w[e].z; acc.w += c * w[e].w;
            }
        }
        __nv_bfloat16 h0 = __float2bfloat16(acc.x);
        __nv_bfloat16 h1 = __float2bfloat16(acc.y);
        __nv_bfloat16 h2 = __float2bfloat16(acc.z);
        __nv_bfloat16 h3 = __float2bfloat16(acc.w);
        __nv_bfloat16 l0 = __float2bfloat16(acc.x - __bfloat162float(h0));
        __nv_bfloat16 l1 = __float2bfloat16(acc.y - __bfloat162float(h1));
        __nv_bfloat16 l2 = __float2bfloat16(acc.z - __bfloat162float(h2));
        __nv_bfloat16 l3 = __float2bfloat16(acc.w - __bfloat162float(h3));
        __nv_bfloat162* hi2 =
            reinterpret_cast<__nv_bfloat162*>(g_whi + (long long)b * OI);
        __nv_bfloat162* lo2 =
            reinterpret_cast<__nv_bfloat162*>(g_wlo + (long long)b * OI);
        hi2[idx * 2 + 0] = __halves2bfloat162(h0, h1);
        hi2[idx * 2 + 1] = __halves2bfloat162(h2, h3);
        lo2[idx * 2 + 0] = __halves2bfloat162(l0, l1);
        lo2[idx * 2 + 1] = __halves2bfloat162(l2, l3);
    }
}

// ---------------------------------------------------------------------------
// Kernel 3: tile table (row tiles confined to one segment each)
// ---------------------------------------------------------------------------
#define BMT 128
#define BNT 128
#define BKT 32
#define NSTAGES 3

__global__ void build_tiles(const int* __restrict__ mole_sizes, int B) {
    if (threadIdx.x != 0 || blockIdx.x != 0) return;
    int cnt = 0, off = 0;
    for (int b = 0; b < B; b++) {
        int sz = mole_sizes[b];
        for (int r = 0; r < sz; r += BMT) {
            if (cnt < MAX_TILES) {
                g_tile_row[cnt] = off + r;
                g_tile_rows[cnt] = (sz - r) < BMT ? (sz - r) : BMT;
                g_tile_seg[cnt] = b;
            }
            cnt++;
        }
        off += sz;
    }
    g_tile_cnt = cnt < MAX_TILES ? cnt : MAX_TILES;
}

// ---------------------------------------------------------------------------
// Kernel 4: bf16 mma.sync GEMM, 128x128 CTA tile, 3-stage cp.async pipeline.
// SMEM per stage: Ahi 8K | Alo 8K | Bhi 8K | Blo 8K = 32KB; 3 stages = 96KB.
// Tile layout: [128 rows][32 cols bf16] = 64B/row, 4x16B chunks,
//   swizzle: chunk' = chunk ^ ((row>>1)&3)  (conflict-free for STS + ldmatrix).
// ---------------------------------------------------------------------------
#define TILE_B   8192
#define STAGE_B  (4 * TILE_B)
#define O_AHI 0
#define O_ALO TILE_B
#define O_BHI (2 * TILE_B)
#define O_BLO (3 * TILE_B)
#define GEMM_SMEM (NSTAGES * STAGE_B)

__device__ __forceinline__ uint32_t swz_off(uint32_t r, uint32_t c) {
    return r * 64u + ((c ^ ((r >> 1) & 3u)) << 4);
}

__device__ __forceinline__ void load_stage(
    uint32_t sbase,
    const __nv_bfloat16* __restrict__ xhi, const __nv_bfloat16* __restrict__ xlo,
    const __nv_bfloat16* __restrict__ whi, const __nv_bfloat16* __restrict__ wlo,
    int row0, int nrows, int col0, int ncols, int I, int k0, int tid) {
#pragma unroll
    for (int t = 0; t < 2; t++) {
        int idx = tid + t * 256;
        int r = idx >> 2;
        int c = idx & 3;
        uint32_t soff = swz_off((uint32_t)r, (uint32_t)c);
        long long gk = (long long)k0 + c * 8;
        {
            int ar = r < nrows ? r : 0;
            int sz = r < nrows ? 16 : 0;
            cp16(sbase + O_AHI + soff, xhi + (long long)(row0 + ar) * I + gk, sz);
            cp16(sbase + O_ALO + soff, xlo + (long long)(row0 + ar) * I + gk, sz);
        }
        {
            int br = r < ncols ? r : 0;
            int sz = r < ncols ? 16 : 0;
            cp16(sbase + O_BHI + soff, whi + (long long)(col0 + br) * I + gk, sz);
            cp16(sbase + O_BLO + soff, wlo + (long long)(col0 + br) * I + gk, sz);
        }
    }
}

__global__ __launch_bounds__(256, 1)
void gemm_kernel(const float* __restrict__ bias,
                 float* __restrict__ y,
                 int I, int O) {
    int t = blockIdx.y;
    if (t >= g_tile_cnt) return;

    extern __shared__ __align__(1024) char smem[];
    uint32_t sm0 = smem_u32(smem);

    const int tid = threadIdx.x;
    const int lane = tid & 31;
    const int wid = tid >> 5;
    const int warp_m = wid & 1;        // 0..1  -> 64 rows each
    const int warp_n = wid >> 1;       // 0..3  -> 32 cols each

    const int row0  = g_tile_row[t];
    const int nrows = g_tile_rows[t];
    const int seg   = g_tile_seg[t];
    const int col0  = blockIdx.x * BNT;
    const long long OI = (long long)O * I;

    const __nv_bfloat16* __restrict__ whi = g_whi + (long long)seg * OI;
    const __nv_bfloat16* __restrict__ wlo = g_wlo + (long long)seg * OI;

    int ncols = O - col0;
    if (ncols > BNT) ncols = BNT;

    // bias registers: this thread's 4 nj groups x 2 cols
    float bj[4][2];
#pragma unroll
    for (int nj = 0; nj < 4; nj++) {
        int cg = col0 + warp_n * 32 + nj * 8 + (lane & 3) * 2;
        bj[nj][0] = (cg < O) ? bias[cg] : 0.f;
        bj[nj][1] = (cg + 1 < O) ? bias[cg + 1] : 0.f;
    }

    float acc[4][4][4];
#pragma unroll
    for (int mi = 0; mi < 4; mi++)
#pragma unroll
        for (int nj = 0; nj < 4; nj++)
#pragma unroll
            for (int q = 0; q < 4; q++) acc[mi][nj][q] = 0.f;

    const int nch = I / BKT;

    // prologue: stages 0..NSTAGES-2
#pragma unroll
    for (int s = 0; s < NSTAGES - 1; s++) {
        load_stage(sm0 + s * STAGE_B, g_xhi, g_xlo, whi, wlo,
                   row0, nrows, col0, ncols, I, s * BKT, tid);
        CP_COMMIT();
    }

    // lane-constant ldmatrix pieces
    const int rlA  = ((lane >> 3) & 1) * 8 + (lane & 7);
    const int chiA = lane >> 4;
    const int rlB  = ((lane >> 4) & 1) * 8 + (lane & 7);
    const int chiB = (lane >> 3) & 1;

    for (int c = 0; c < nch; c++) {
        CP_WAIT(NSTAGES - 2);
        __syncthreads();

        int pf = c + NSTAGES - 1;
        if (pf < nch) {
            load_stage(sm0 + (pf % NSTAGES) * STAGE_B, g_xhi, g_xlo, whi, wlo,
                       row0, nrows, col0, ncols, I, pf * BKT, tid);
        }
        CP_COMMIT();

        uint32_t sb = sm0 + (c % NSTAGES) * STAGE_B;

#pragma unroll
        for (int ks = 0; ks < 2; ks++) {
            uint32_t ahi[4][4], alo[4][4], bh[2][4], bl[2][4];
#pragma unroll
            for (int mi = 0; mi < 4; mi++) {
                uint32_t r = (uint32_t)(warp_m * 64 + mi * 16 + rlA);
                uint32_t cc = (uint32_t)(ks * 2 + chiA);
                uint32_t off = swz_off(r, cc);
                ldm4(ahi[mi], sb + O_AHI + off);
                ldm4(alo[mi], sb + O_ALO + off);
            }
#pragma unroll
            for (int g = 0; g < 2; g++) {
                uint32_t r = (uint32_t)(warp_n * 32 + g * 16 + rlB);
                uint32_t cc = (uint32_t)(ks * 2 + chiB);
                uint32_t off = swz_off(r, cc);
                ldm4(bh[g], sb + O_BHI + off);
                ldm4(bl[g], sb + O_BLO + off);
            }
#pragma unroll
            for (int mi = 0; mi < 4; mi++) {
#pragma unroll
                for (int nj = 0; nj < 4; nj++) {
                    int g = nj >> 1;
                    int p = (nj & 1) * 2;
                    mma_bf16(acc[mi][nj], ahi[mi], bh[g][p], bh[g][p + 1]);
                    mma_bf16(acc[mi][nj], ahi[mi], bl[g][p], bl[g][p + 1]);
                    mma_bf16(acc[mi][nj], alo[mi], bh[g][p], bh[g][p + 1]);
                }
            }
        }
    }

    // epilogue: add bias, store fp32
#pragma unroll
    for (int mi = 0; mi < 4; mi++) {
        int rA = warp_m * 64 + mi * 16 + (lane >> 2);
        int rB = rA + 8;
#pragma unroll
        for (int nj = 0; nj < 4; nj++) {
            int cg = col0 + warp_n * 32 + nj * 8 + (lane & 3) * 2;
            int cl = cg - col0;
            bool c2 = (cl + 2 <= ncols);
            bool c1 = (cl < ncols);
            if (rA < nrows) {
                long long base = (long long)(row0 + rA) * O + cg;
                if (c2) {
                    float2 v = make_float2(acc[mi][nj][0] + bj[nj][0],
                                           acc[mi][nj][1] + bj[nj][1]);
                    *reinterpret_cast<float2*>(y + base) = v;
                } else if (c1) {
                    y[base] = acc[mi][nj][0] + bj[nj][0];
                }
            }
            if (rB < nrows) {
                long long base = (long long)(row0 + rB) * O + cg;
                if (c2) {
                    float2 v = make_float2(acc[mi][nj][2] + bj[nj][0],
                                           acc[mi][nj][3] + bj[nj][1]);
                    *reinterpret_cast<float2*>(y + base) = v;
                } else if (c1) {
                    y[base] = acc[mi][nj][2] + bj[nj][0];
                }
            }
        }
    }
}

// ---------------------------------------------------------------------------
// Launch
// ---------------------------------------------------------------------------
extern "C" void kernel_launch(void* const* d_in, const int* in_sizes, int n_in,
                              void* d_out, int out_size) {
    const float* x     = (const float*)d_in[0];   // [N, I]
    const float* W     = (const float*)d_in[1];   // [E, O, I]
    const float* bias  = (const float*)d_in[2];   // [O]
    const float* coeff = (const float*)d_in[3];   // [B, E]
    const int*   msize = (const int*)  d_in[4];   // [B]

    const int O = in_sizes[2];
    const int N = out_size / O;
    const int I = in_sizes[0] / N;
    const int E = in_sizes[1] / (O * I);
    const int B = in_sizes[3] / E;

    // 1) split x
    {
        long long n4 = (long long)N * I / 4;
        int threads = 256;
        int blocks = (int)((n4 + threads - 1) / threads);
        split_x_kernel<<<blocks, threads>>>(x, n4);
    }
    // 2) mix weights
    {
        long long OI4 = (long long)O * I / 4;
        int threads = 256;
        int blocks = (int)((OI4 + threads - 1) / threads);
        mix_kernel<<<blocks, threads>>>(W, coeff, E, B, OI4);
    }
    // 3) tile table
    build_tiles<<<1, 32>>>(msize, B);

    // 4) GEMM
    {
        static bool attr_set = false;
        if (!attr_set) {
            cudaFuncSetAttribute(gemm_kernel,
                                 cudaFuncAttributeMaxDynamicSharedMemorySize,
                                 GEMM_SMEM);
            attr_set = true;
        }
        int maxTiles = (N + BMT - 1) / BMT + B;
        dim3 grid((O + BNT - 1) / BNT, maxTiles);
        gemm_kernel<<<grid, 256, GEMM_SMEM>>>(bias, (float*)d_out, I, O);
    }
}

// round 4
// speedup vs baseline: 3.1083x; 1.1165x over previous
#include <cuda_runtime.h>
#include <cuda_bf16.h>
#include <cstdint>

// ===========================================================================
// MoE segment-linear via mma.sync bf16 split-precision GEMM (plain-sm_103 ISA).
//   y[n,o] = sum_e coeff[seg(n),e] * dot(x[n,:], W[e,o,:]) + bias[o]
// prep (fused): split x into bf16 hi/lo, mix weights -> bf16 hi/lo, tile table
// gemm: D = Ahi*Bhi + Ahi*Blo + Alo*Bhi (fp32 reg accum) + bias
// ===========================================================================

#define MAX_X_ELEMS (16u * 1024u * 1024u)   // N*I
#define MAX_W_ELEMS (16u * 1024u * 1024u)   // B*O*I
#define MAX_TILES 4096
#define MAX_COEFF 512

__device__ __nv_bfloat16 g_xhi[MAX_X_ELEMS];
__device__ __nv_bfloat16 g_xlo[MAX_X_ELEMS];
__device__ __nv_bfloat16 g_whi[MAX_W_ELEMS];
__device__ __nv_bfloat16 g_wlo[MAX_W_ELEMS];
__device__ int g_tile_row[MAX_TILES];
__device__ int g_tile_rows[MAX_TILES];
__device__ int g_tile_seg[MAX_TILES];
__device__ int g_tile_cnt;

// ---------------------------------------------------------------------------
// Helpers (baseline PTX only)
// ---------------------------------------------------------------------------
__device__ __forceinline__ uint32_t smem_u32(const void* p) {
    uint32_t a;
    asm("{ .reg .u64 t; cvta.to.shared.u64 t, %1; cvt.u32.u64 %0, t; }"
        : "=r"(a) : "l"(p));
    return a;
}
__device__ __forceinline__ void cp16(uint32_t dst, const void* src, int szbytes) {
    asm volatile("cp.async.cg.shared.global [%0], [%1], 16, %2;"
                 :: "r"(dst), "l"(src), "r"(szbytes));
}
#define CP_COMMIT() asm volatile("cp.async.commit_group;")
#define CP_WAIT(n)  asm volatile("cp.async.wait_group %0;" :: "n"(n))

__device__ __forceinline__ void ldm4(uint32_t* r, uint32_t addr) {
    asm volatile("ldmatrix.sync.aligned.m8n8.x4.shared.b16 {%0,%1,%2,%3}, [%4];"
                 : "=r"(r[0]), "=r"(r[1]), "=r"(r[2]), "=r"(r[3]) : "r"(addr));
}
__device__ __forceinline__ void mma_bf16(float* c, const uint32_t* a,
                                         uint32_t b0, uint32_t b1) {
    asm volatile(
        "mma.sync.aligned.m16n8k16.row.col.f32.bf16.bf16.f32 "
        "{%0,%1,%2,%3}, {%4,%5,%6,%7}, {%8,%9}, {%0,%1,%2,%3};"
        : "+f"(c[0]), "+f"(c[1]), "+f"(c[2]), "+f"(c[3])
        : "r"(a[0]), "r"(a[1]), "r"(a[2]), "r"(a[3]), "r"(b0), "r"(b1));
}

// ---------------------------------------------------------------------------
// Fused prep kernel.
//   blocks [0, xb)          : split x -> g_xhi/g_xlo
//   blocks [xb, xb+wb)      : mix W   -> g_whi/g_wlo
//   block  xb+wb            : tile table
// ---------------------------------------------------------------------------
#define BMT 128
#define BNT 128
#define BKT 32
#define NSTAGES 3

__global__ void prep_kernel(const float* __restrict__ x,
                            const float* __restrict__ W,
                            const float* __restrict__ coeff,
                            const int* __restrict__ mole_sizes,
                            int E, int B, long long n4 /*x float4s*/,
                            long long OI4, int xb, int wb) {
    int bid = blockIdx.x;
    if (bid < xb) {
        long long idx = (long long)bid * blockDim.x + threadIdx.x;
        if (idx >= n4) return;
        float4 v = reinterpret_cast<const float4*>(x)[idx];
        __nv_bfloat16 h0 = __float2bfloat16(v.x);
        __nv_bfloat16 h1 = __float2bfloat16(v.y);
        __nv_bfloat16 h2 = __float2bfloat16(v.z);
        __nv_bfloat16 h3 = __float2bfloat16(v.w);
        __nv_bfloat16 l0 = __float2bfloat16(v.x - __bfloat162float(h0));
        __nv_bfloat16 l1 = __float2bfloat16(v.y - __bfloat162float(h1));
        __nv_bfloat16 l2 = __float2bfloat16(v.z - __bfloat162float(h2));
        __nv_bfloat16 l3 = __float2bfloat16(v.w - __bfloat162float(h3));
        __nv_bfloat162* hi2 = reinterpret_cast<__nv_bfloat162*>(g_xhi);
        __nv_bfloat162* lo2 = reinterpret_cast<__nv_bfloat162*>(g_xlo);
        hi2[idx * 2 + 0] = __halves2bfloat162(h0, h1);
        hi2[idx * 2 + 1] = __halves2bfloat162(h2, h3);
        lo2[idx * 2 + 0] = __halves2bfloat162(l0, l1);
        lo2[idx * 2 + 1] = __halves2bfloat162(l2, l3);
        return;
    }
    if (bid < xb + wb) {
        long long idx = (long long)(bid - xb) * blockDim.x + threadIdx.x;
        __shared__ float sc[MAX_COEFF];
        int ncoef = B * E;
        for (int i = threadIdx.x; i < ncoef; i += blockDim.x) sc[i] = coeff[i];
        __syncthreads();
        if (idx >= OI4) return;

        float4 w[8];
#pragma unroll
        for (int e = 0; e < 8; e++) {
            if (e < E)
                w[e] = reinterpret_cast<const float4*>(W)[(long long)e * OI4 + idx];
            else
                w[e] = make_float4(0.f, 0.f, 0.f, 0.f);
        }
        long long OI = OI4 * 4;
        for (int b = 0; b < B; b++) {
            float4 acc = make_float4(0.f, 0.f, 0.f, 0.f);
#pragma unroll
            for (int e = 0; e < 8; e++) {
                if (e < E) {
                    float c = sc[b * E + e];
                    acc.x += c * w[e].x; acc.y += c * w[e].y;
                    acc.z += c * w[e].z; acc.w += c * w[e].w;
                }
            }
            __nv_bfloat16 h0 = __float2bfloat16(acc.x);
            __nv_bfloat16 h1 = __float2bfloat16(acc.y);
            __nv_bfloat16 h2 = __float2bfloat16(acc.z);
            __nv_bfloat16 h3 = __float2bfloat16(acc.w);
            __nv_bfloat16 l0 = __float2bfloat16(acc.x - __bfloat162float(h0));
            __nv_bfloat16 l1 = __float2bfloat16(acc.y - __bfloat162float(h1));
            __nv_bfloat16 l2 = __float2bfloat16(acc.z - __bfloat162float(h2));
            __nv_bfloat16 l3 = __float2bfloat16(acc.w - __bfloat162float(h3));
            __nv_bfloat162* hi2 =
                reinterpret_cast<__nv_bfloat162*>(g_whi + (long long)b * OI);
            __nv_bfloat162* lo2 =
                reinterpret_cast<__nv_bfloat162*>(g_wlo + (long long)b * OI);
            hi2[idx * 2 + 0] = __halves2bfloat162(h0, h1);
            hi2[idx * 2 + 1] = __halves2bfloat162(h2, h3);
            lo2[idx * 2 + 0] = __halves2bfloat162(l0, l1);
            lo2[idx * 2 + 1] = __halves2bfloat162(l2, l3);
        }
        return;
    }
    // tile table
    if (threadIdx.x == 0) {
        int cnt = 0, off = 0;
        for (int b = 0; b < B; b++) {
            int sz = mole_sizes[b];
            for (int r = 0; r < sz; r += BMT) {
                if (cnt < MAX_TILES) {
                    g_tile_row[cnt] = off + r;
                    g_tile_rows[cnt] = (sz - r) < BMT ? (sz - r) : BMT;
                    g_tile_seg[cnt] = b;
                }
                cnt++;
            }
            off += sz;
        }
        g_tile_cnt = cnt < MAX_TILES ? cnt : MAX_TILES;
    }
}

// ---------------------------------------------------------------------------
// GEMM: bf16 mma.sync, 128x128 CTA tile, 3-stage cp.async pipeline,
// 2 CTAs per SM (launch_bounds caps regs at 128).
// SMEM per stage: Ahi 8K | Alo 8K | Bhi 8K | Blo 8K = 32KB; 3 stages = 96KB.
// ---------------------------------------------------------------------------
#define TILE_B   8192
#define STAGE_B  (4 * TILE_B)
#define O_AHI 0
#define O_ALO TILE_B
#define O_BHI (2 * TILE_B)
#define O_BLO (3 * TILE_B)
#define GEMM_SMEM (NSTAGES * STAGE_B)

__device__ __forceinline__ uint32_t swz_off(uint32_t r, uint32_t c) {
    return r * 64u + ((c ^ ((r >> 1) & 3u)) << 4);
}

__device__ __forceinline__ void load_stage(
    uint32_t sbase,
    const __nv_bfloat16* __restrict__ xhi, const __nv_bfloat16* __restrict__ xlo,
    const __nv_bfloat16* __restrict__ whi, const __nv_bfloat16* __restrict__ wlo,
    int row0, int nrows, int col0, int ncols, int I, int k0, int tid) {
#pragma unroll
    for (int t = 0; t < 2; t++) {
        int idx = tid + t * 256;
        int r = idx >> 2;
        int c = idx & 3;
        uint32_t soff = swz_off((uint32_t)r, (uint32_t)c);
        long long gk = (long long)k0 + c * 8;
        {
            int ar = r < nrows ? r : 0;
            int sz = r < nrows ? 16 : 0;
            cp16(sbase + O_AHI + soff, xhi + (long long)(row0 + ar) * I + gk, sz);
            cp16(sbase + O_ALO + soff, xlo + (long long)(row0 + ar) * I + gk, sz);
        }
        {
            int br = r < ncols ? r : 0;
            int sz = r < ncols ? 16 : 0;
            cp16(sbase + O_BHI + soff, whi + (long long)(col0 + br) * I + gk, sz);
            cp16(sbase + O_BLO + soff, wlo + (long long)(col0 + br) * I + gk, sz);
        }
    }
}

__global__ __launch_bounds__(256, 2)
void gemm_kernel(const float* __restrict__ bias,
                 float* __restrict__ y,
                 int I, int O) {
    int t = blockIdx.y;
    if (t >= g_tile_cnt) return;

    extern __shared__ __align__(1024) char smem[];
    uint32_t sm0 = smem_u32(smem);

    const int tid = threadIdx.x;
    const int lane = tid & 31;
    const int wid = tid >> 5;
    const int warp_m = wid & 1;        // 0..1  -> 64 rows each
    const int warp_n = wid >> 1;       // 0..3  -> 32 cols each

    const int row0  = g_tile_row[t];
    const int nrows = g_tile_rows[t];
    const int seg   = g_tile_seg[t];
    const int col0  = blockIdx.x * BNT;
    const long long OI = (long long)O * I;

    const __nv_bfloat16* __restrict__ whi = g_whi + (long long)seg * OI;
    const __nv_bfloat16* __restrict__ wlo = g_wlo + (long long)seg * OI;

    int ncols = O - col0;
    if (ncols > BNT) ncols = BNT;

    float acc[4][4][4];
#pragma unroll
    for (int mi = 0; mi < 4; mi++)
#pragma unroll
        for (int nj = 0; nj < 4; nj++)
#pragma unroll
            for (int q = 0; q < 4; q++) acc[mi][nj][q] = 0.f;

    const int nch = I / BKT;

#pragma unroll
    for (int s = 0; s < NSTAGES - 1; s++) {
        load_stage(sm0 + s * STAGE_B, g_xhi, g_xlo, whi, wlo,
                   row0, nrows, col0, ncols, I, s * BKT, tid);
        CP_COMMIT();
    }

    const int rlA  = ((lane >> 3) & 1) * 8 + (lane & 7);
    const int chiA = lane >> 4;
    const int rlB  = ((lane >> 4) & 1) * 8 + (lane & 7);
    const int chiB = (lane >> 3) & 1;

    for (int c = 0; c < nch; c++) {
        CP_WAIT(NSTAGES - 2);
        __syncthreads();

        int pf = c + NSTAGES - 1;
        if (pf < nch) {
            load_stage(sm0 + (pf % NSTAGES) * STAGE_B, g_xhi, g_xlo, whi, wlo,
                       row0, nrows, col0, ncols, I, pf * BKT, tid);
        }
        CP_COMMIT();

        uint32_t sb = sm0 + (c % NSTAGES) * STAGE_B;

#pragma unroll
        for (int ks = 0; ks < 2; ks++) {
            uint32_t ahi[4][4], alo[4][4], bh[2][4], bl[2][4];
#pragma unroll
            for (int mi = 0; mi < 4; mi++) {
                uint32_t r = (uint32_t)(warp_m * 64 + mi * 16 + rlA);
                uint32_t cc = (uint32_t)(ks * 2 + chiA);
                uint32_t off = swz_off(r, cc);
                ldm4(ahi[mi], sb + O_AHI + off);
                ldm4(alo[mi], sb + O_ALO + off);
            }
#pragma unroll
            for (int g = 0; g < 2; g++) {
                uint32_t r = (uint32_t)(warp_n * 32 + g * 16 + rlB);
                uint32_t cc = (uint32_t)(ks * 2 + chiB);
                uint32_t off = swz_off(r, cc);
                ldm4(bh[g], sb + O_BHI + off);
                ldm4(bl[g], sb + O_BLO + off);
            }
#pragma unroll
            for (int mi = 0; mi < 4; mi++) {
#pragma unroll
                for (int nj = 0; nj < 4; nj++) {
                    int g = nj >> 1;
                    int p = (nj & 1) * 2;
                    mma_bf16(acc[mi][nj], ahi[mi], bh[g][p], bh[g][p + 1]);
                    mma_bf16(acc[mi][nj], ahi[mi], bl[g][p], bl[g][p + 1]);
                    mma_bf16(acc[mi][nj], alo[mi], bh[g][p], bh[g][p + 1]);
                }
            }
        }
    }

    // epilogue: add bias (loaded here to keep mainloop reg pressure low), store
#pragma unroll
    for (int mi = 0; mi < 4; mi++) {
        int rA = warp_m * 64 + mi * 16 + (lane >> 2);
        int rB = rA + 8;
#pragma unroll
        for (int nj = 0; nj < 4; nj++) {
            int cg = col0 + warp_n * 32 + nj * 8 + (lane & 3) * 2;
            int cl = cg - col0;
            bool c2 = (cl + 2 <= ncols);
            bool c1 = (cl < ncols);
            float b0 = (cg < O) ? bias[cg] : 0.f;
            float b1 = (cg + 1 < O) ? bias[cg + 1] : 0.f;
            if (rA < nrows) {
                long long base = (long long)(row0 + rA) * O + cg;
                if (c2) {
                    float2 v = make_float2(acc[mi][nj][0] + b0,
                                           acc[mi][nj][1] + b1);
                    *reinterpret_cast<float2*>(y + base) = v;
                } else if (c1) {
                    y[base] = acc[mi][nj][0] + b0;
                }
            }
            if (rB < nrows) {
                long long base = (long long)(row0 + rB) * O + cg;
                if (c2) {
                    float2 v = make_float2(acc[mi][nj][2] + b0,
                                           acc[mi][nj][3] + b1);
                    *reinterpret_cast<float2*>(y + base) = v;
                } else if (c1) {
                    y[base] = acc[mi][nj][2] + b0;
                }
            }
        }
    }
}

// ---------------------------------------------------------------------------
// Launch
// ---------------------------------------------------------------------------
extern "C" void kernel_launch(void* const* d_in, const int* in_sizes, int n_in,
                              void* d_out, int out_size) {
    const float* x     = (const float*)d_in[0];   // [N, I]
    const float* W     = (const float*)d_in[1];   // [E, O, I]
    const float* bias  = (const float*)d_in[2];   // [O]
    const float* coeff = (const float*)d_in[3];   // [B, E]
    const int*   msize = (const int*)  d_in[4];   // [B]

    const int O = in_sizes[2];
    const int N = out_size / O;
    const int I = in_sizes[0] / N;
    const int E = in_sizes[1] / (O * I);
    const int B = in_sizes[3] / E;

    // fused prep
    {
        long long n4 = (long long)N * I / 4;
        long long OI4 = (long long)O * I / 4;
        int threads = 256;
        int xb = (int)((n4 + threads - 1) / threads);
        int wb = (int)((OI4 + threads - 1) / threads);
        prep_kernel<<<xb + wb + 1, threads>>>(x, W, coeff, msize,
                                              E, B, n4, OI4, xb, wb);
    }

    // GEMM
    {
        static bool attr_set = false;
        if (!attr_set) {
            cudaFuncSetAttribute(gemm_kernel,
                                 cudaFuncAttributeMaxDynamicSharedMemorySize,
                                 GEMM_SMEM);
            attr_set = true;
        }
        int maxTiles = (N + BMT - 1) / BMT + B;
        dim3 grid((O + BNT - 1) / BNT, maxTiles);
        gemm_kernel<<<grid, 256, GEMM_SMEM>>>(bias, (float*)d_out, I, O);
    }
}